// round 3
// baseline (speedup 1.0000x reference)
#include <cuda_runtime.h>
#include <cstdint>

#define THREADS 512
#define ELEMS   16384
#define VEC_ITER (ELEMS / 4 / THREADS)   // 8 float4 per thread
#define KSEL    32
#define CAP     4096
#define THRESH  1.75f

// Order-preserving float -> uint32 key (ascending float <-> ascending unsigned)
__device__ __forceinline__ unsigned f2key(float f) {
    unsigned u = __float_as_uint(f);
    return (u & 0x80000000u) ? ~u : (u | 0x80000000u);
}
// relu(value) recovered from key
__device__ __forceinline__ float key2relu(unsigned k) {
    return (k & 0x80000000u) ? __uint_as_float(k ^ 0x80000000u) : 0.0f;
}

__global__ __launch_bounds__(THREADS)
void splittopk_kernel(const float* __restrict__ x, float* __restrict__ out)
{
    __shared__ unsigned       ckeys[CAP];   // 16 KB
    __shared__ unsigned short cidx[CAP];    //  8 KB
    __shared__ unsigned hist[256];
    __shared__ int s_cnt;
    __shared__ unsigned s_prefix;
    __shared__ int s_k;
    __shared__ int s_eqcnt;
    __shared__ int eq_idx[64];

    const int tid = threadIdx.x;
    const long long base = (long long)blockIdx.x * ELEMS;
    const float4* __restrict__ x4 = (const float4*)(x + base);

    if (tid == 0) { s_cnt = 0; s_prefix = 0u; s_k = KSEL; s_eqcnt = 0; }
    __syncthreads();

    // ---- Phase 1: front-batched loads (max MLP), streaming hint ----
    float4 r[VEC_ITER];
    #pragma unroll
    for (int j = 0; j < VEC_ITER; ++j)
        r[j] = __ldcs(&x4[j * THREADS + tid]);

    // ---- Phase 2: ballot-free candidate compaction ----
    #pragma unroll
    for (int j = 0; j < VEC_ITER; ++j) {
        const int p = j * THREADS + tid;
        float vv[4] = {r[j].x, r[j].y, r[j].z, r[j].w};
        int nc = (vv[0] > THRESH) + (vv[1] > THRESH) +
                 (vv[2] > THRESH) + (vv[3] > THRESH);
        if (nc) {
            int pos = atomicAdd(&s_cnt, nc);
            #pragma unroll
            for (int c = 0; c < 4; ++c) {
                if (vv[c] > THRESH) {
                    if (pos < CAP) {
                        ckeys[pos] = f2key(vv[c]);
                        cidx[pos]  = (unsigned short)(p * 4 + c);
                    }
                    ++pos;
                }
            }
        }
    }
    __syncthreads();

    const int cnt = s_cnt;

    if (cnt >= KSEL && cnt <= CAP) {
        // ======== FAST PATH: exact radix-select over ~hundreds of candidates ====
        #pragma unroll
        for (int pass = 0; pass < 4; ++pass) {
            const int shift = 24 - pass * 8;
            if (tid < 256) hist[tid] = 0u;
            __syncthreads();
            const unsigned pmask = (pass == 0) ? 0u : (0xFFFFFFFFu << (shift + 8));
            const unsigned pfx = s_prefix;
            for (int i = tid; i < cnt; i += THREADS) {
                unsigned k = ckeys[i];
                if ((k & pmask) == pfx)
                    atomicAdd(&hist[(k >> shift) & 255u], 1u);
            }
            __syncthreads();
            if (tid == 0) {
                int acc = 0; int b = 255;
                for (; b > 0; --b) {
                    int h = (int)hist[b];
                    if (acc + h >= s_k) break;
                    acc += h;
                }
                s_prefix = pfx | ((unsigned)b << shift);
                s_k -= acc;
            }
            __syncthreads();
        }
        const unsigned T = s_prefix;
        const int kneed  = s_k;
        const float vT   = key2relu(T);

        for (int i = tid; i < cnt; i += THREADS) {
            unsigned k = ckeys[i];
            if (k > T) {
                out[base + cidx[i]] = key2relu(k);
            } else if (k == T) {
                int pq = atomicAdd(&s_eqcnt, 1);
                if (pq < 64) eq_idx[pq] = cidx[i];
            }
        }
        __syncthreads();

        const int eqc = s_eqcnt;
        if (eqc == kneed) {
            if (tid < eqc) out[base + eq_idx[tid]] = vT;
        } else {
            // fp32 tie at threshold: keep kneed smallest original indices
            for (int i = tid; i < cnt; i += THREADS) {
                if (ckeys[i] == T) {
                    int my = cidx[i];
                    int rank = 0;
                    for (int j = 0; j < cnt; ++j)
                        rank += (ckeys[j] == T && cidx[j] < my);
                    if (rank < kneed) out[base + my] = vT;
                }
            }
        }
    } else {
        // ======== COLD PATH: exact full radix-select reading from global ========
        #pragma unroll
        for (int pass = 0; pass < 4; ++pass) {
            const int shift = 24 - pass * 8;
            if (tid < 256) hist[tid] = 0u;
            __syncthreads();
            const unsigned pmask = (pass == 0) ? 0u : (0xFFFFFFFFu << (shift + 8));
            const unsigned pfx = s_prefix;
            for (int i = tid; i < ELEMS; i += THREADS) {
                unsigned k = f2key(x[base + i]);
                if ((k & pmask) == pfx)
                    atomicAdd(&hist[(k >> shift) & 255u], 1u);
            }
            __syncthreads();
            if (tid == 0) {
                int acc = 0; int b = 255;
                for (; b > 0; --b) {
                    int h = (int)hist[b];
                    if (acc + h >= s_k) break;
                    acc += h;
                }
                s_prefix = pfx | ((unsigned)b << shift);
                s_k -= acc;
            }
            __syncthreads();
        }
        const unsigned T = s_prefix;
        const int kneed  = s_k;
        const float vT   = key2relu(T);

        for (int i = tid; i < ELEMS; i += THREADS) {
            unsigned k = f2key(x[base + i]);
            if (k > T) {
                out[base + i] = key2relu(k);
            } else if (k == T) {
                int pq = atomicAdd(&s_eqcnt, 1);
                if (pq < 64) eq_idx[pq] = i;
            }
        }
        __syncthreads();

        const int eqc = s_eqcnt;
        if (eqc == kneed) {
            if (tid < eqc) out[base + eq_idx[tid]] = vT;
        } else {
            for (int i = tid; i < ELEMS; i += THREADS) {
                if (f2key(x[base + i]) == T) {
                    int rank = 0;
                    for (int j = 0; j < i; ++j) rank += (f2key(x[base + j]) == T);
                    if (rank < kneed) out[base + i] = vT;
                }
            }
        }
    }
}

extern "C" void kernel_launch(void* const* d_in, const int* in_sizes, int n_in,
                              void* d_out, int out_size) {
    const float* x = (const float*)d_in[0];
    float* out = (float*)d_out;

    // Zero the whole output via a memset node (graph-capturable, near-peak BW).
    cudaMemsetAsync(d_out, 0, (size_t)out_size * sizeof(float));

    int nblocks = out_size / ELEMS;   // 4096 rows * 2 partitions = 8192
    splittopk_kernel<<<nblocks, THREADS>>>(x, out);
}

// round 4
// speedup vs baseline: 2.1988x; 2.1988x over previous
#include <cuda_runtime.h>
#include <cstdint>

#define THREADS 512
#define ELEMS   16384
#define VEC_ITER (ELEMS / 4 / THREADS)   // 8 float4 per thread
#define KSEL    32
#define CAP     4096
#define THRESH  1.75f

// Order-preserving float -> uint32 key (ascending float <-> ascending unsigned)
__device__ __forceinline__ unsigned f2key(float f) {
    unsigned u = __float_as_uint(f);
    return (u & 0x80000000u) ? ~u : (u | 0x80000000u);
}
// relu(value) recovered from key
__device__ __forceinline__ float key2relu(unsigned k) {
    return (k & 0x80000000u) ? __uint_as_float(k ^ 0x80000000u) : 0.0f;
}

// Warp-parallel selection of the radix bin: finds unique b with
// F(b) >= k > F(b+1), where F(b) = sum_{j>=b} hist[j]. Warp 0 only.
__device__ __forceinline__ void select_bin(const unsigned* hist,
                                           volatile unsigned* s_prefix,
                                           volatile int* s_k,
                                           unsigned pfx, int shift, int tid)
{
    if (tid < 32) {
        const int lane = tid;
        unsigned hh[8];
        int lsum = 0;
        #pragma unroll
        for (int c = 0; c < 8; ++c) { hh[c] = hist[lane * 8 + c]; lsum += (int)hh[c]; }
        // inclusive suffix-sum across lanes (lane gets sum over lanes >= lane)
        int suf = lsum;
        #pragma unroll
        for (int off = 1; off < 32; off <<= 1) {
            int v = __shfl_down_sync(0xFFFFFFFFu, suf, off);
            if (lane + off < 32) suf += v;
        }
        const int above = suf - lsum;      // sum over lanes > lane
        const int k = *s_k;                // read before any lane writes
        int F = above;                     // F(b+1) running from top of chunk
        int foundb = -1, Fnext_at_found = 0;
        #pragma unroll
        for (int c = 7; c >= 0; --c) {
            int Fnext = F;
            F += (int)hh[c];               // F(b) for b = lane*8+c
            if (F >= k && Fnext < k) { foundb = lane * 8 + c; Fnext_at_found = Fnext; }
        }
        if (foundb >= 0) {                 // exactly one lane matches
            *s_prefix = pfx | ((unsigned)foundb << shift);
            *s_k = k - Fnext_at_found;
        }
    }
}

__global__ __launch_bounds__(THREADS)
void splittopk_kernel(const float* __restrict__ x, float* __restrict__ out)
{
    __shared__ unsigned       ckeys[CAP];   // 16 KB
    __shared__ unsigned short cidx[CAP];    //  8 KB
    __shared__ unsigned hist[256];
    __shared__ int s_cnt;
    __shared__ unsigned s_prefix;
    __shared__ int s_k;
    __shared__ int s_eqcnt;
    __shared__ int eq_idx[64];

    const int tid = threadIdx.x;
    const long long base = (long long)blockIdx.x * ELEMS;
    const float4* __restrict__ x4 = (const float4*)(x + base);
    float4* __restrict__ o4 = (float4*)(out + base);

    if (tid == 0) { s_cnt = 0; s_prefix = 0u; s_k = KSEL; s_eqcnt = 0; }
    __syncthreads();

    // ---- Phase 1: front-batched loads; zero stores issue under load shadow ----
    float4 r[VEC_ITER];
    #pragma unroll
    for (int j = 0; j < VEC_ITER; ++j)
        r[j] = __ldcs(&x4[j * THREADS + tid]);
    #pragma unroll
    for (int j = 0; j < VEC_ITER; ++j)
        o4[j * THREADS + tid] = make_float4(0.f, 0.f, 0.f, 0.f);

    // ---- Phase 2: ballot-free candidate compaction ----
    #pragma unroll
    for (int j = 0; j < VEC_ITER; ++j) {
        const int p = j * THREADS + tid;
        float vv[4] = {r[j].x, r[j].y, r[j].z, r[j].w};
        int nc = (vv[0] > THRESH) + (vv[1] > THRESH) +
                 (vv[2] > THRESH) + (vv[3] > THRESH);
        if (nc) {
            int pos = atomicAdd(&s_cnt, nc);
            #pragma unroll
            for (int c = 0; c < 4; ++c) {
                if (vv[c] > THRESH) {
                    if (pos < CAP) {
                        ckeys[pos] = f2key(vv[c]);
                        cidx[pos]  = (unsigned short)(p * 4 + c);
                    }
                    ++pos;
                }
            }
        }
    }
    __syncthreads();

    const int cnt = s_cnt;

    if (cnt >= KSEL && cnt <= CAP) {
        // ======== FAST PATH: radix-select over ~hundreds of candidates ========
        #pragma unroll
        for (int pass = 0; pass < 4; ++pass) {
            const int shift = 24 - pass * 8;
            if (tid < 256) hist[tid] = 0u;
            __syncthreads();
            const unsigned pmask = (pass == 0) ? 0u : (0xFFFFFFFFu << (shift + 8));
            const unsigned pfx = s_prefix;
            for (int i = tid; i < cnt; i += THREADS) {
                unsigned k = ckeys[i];
                if ((k & pmask) == pfx)
                    atomicAdd(&hist[(k >> shift) & 255u], 1u);
            }
            __syncthreads();
            select_bin(hist, &s_prefix, &s_k, pfx, shift, tid);
            __syncthreads();
        }
        const unsigned T = s_prefix;
        const int kneed  = s_k;
        const float vT   = key2relu(T);

        for (int i = tid; i < cnt; i += THREADS) {
            unsigned k = ckeys[i];
            if (k > T) {
                out[base + cidx[i]] = key2relu(k);
            } else if (k == T) {
                int pq = atomicAdd(&s_eqcnt, 1);
                if (pq < 64) eq_idx[pq] = cidx[i];
            }
        }
        __syncthreads();

        const int eqc = s_eqcnt;
        if (eqc == kneed) {
            if (tid < eqc) out[base + eq_idx[tid]] = vT;
        } else {
            // fp32 tie at threshold: keep kneed smallest original indices
            for (int i = tid; i < cnt; i += THREADS) {
                if (ckeys[i] == T) {
                    int my = cidx[i];
                    int rank = 0;
                    for (int j = 0; j < cnt; ++j)
                        rank += (ckeys[j] == T && cidx[j] < my);
                    if (rank < kneed) out[base + my] = vT;
                }
            }
        }
    } else {
        // ======== COLD PATH: exact full radix-select reading from global ========
        #pragma unroll
        for (int pass = 0; pass < 4; ++pass) {
            const int shift = 24 - pass * 8;
            if (tid < 256) hist[tid] = 0u;
            __syncthreads();
            const unsigned pmask = (pass == 0) ? 0u : (0xFFFFFFFFu << (shift + 8));
            const unsigned pfx = s_prefix;
            for (int i = tid; i < ELEMS; i += THREADS) {
                unsigned k = f2key(x[base + i]);
                if ((k & pmask) == pfx)
                    atomicAdd(&hist[(k >> shift) & 255u], 1u);
            }
            __syncthreads();
            select_bin(hist, &s_prefix, &s_k, pfx, shift, tid);
            __syncthreads();
        }
        const unsigned T = s_prefix;
        const int kneed  = s_k;
        const float vT   = key2relu(T);

        for (int i = tid; i < ELEMS; i += THREADS) {
            unsigned k = f2key(x[base + i]);
            if (k > T) {
                out[base + i] = key2relu(k);
            } else if (k == T) {
                int pq = atomicAdd(&s_eqcnt, 1);
                if (pq < 64) eq_idx[pq] = i;
            }
        }
        __syncthreads();

        const int eqc = s_eqcnt;
        if (eqc == kneed) {
            if (tid < eqc) out[base + eq_idx[tid]] = vT;
        } else {
            for (int i = tid; i < ELEMS; i += THREADS) {
                if (f2key(x[base + i]) == T) {
                    int rank = 0;
                    for (int j = 0; j < i; ++j) rank += (f2key(x[base + j]) == T);
                    if (rank < kneed) out[base + i] = vT;
                }
            }
        }
    }
}

extern "C" void kernel_launch(void* const* d_in, const int* in_sizes, int n_in,
                              void* d_out, int out_size) {
    const float* x = (const float*)d_in[0];
    float* out = (float*)d_out;
    int nblocks = out_size / ELEMS;   // 4096 rows * 2 partitions = 8192
    splittopk_kernel<<<nblocks, THREADS>>>(x, out);
}

// round 5
// speedup vs baseline: 2.6303x; 1.1963x over previous
#include <cuda_runtime.h>
#include <cstdint>

#define THREADS 512
#define ELEMS   16384
#define CHUNK   4                          // float4 per thread per chunk
#define NCHUNK  (ELEMS / 4 / THREADS / CHUNK)   // 2 chunks
#define KSEL    32
#define CAP     2048
#define THRESH  1.75f

// Order-preserving float -> uint32 key (ascending float <-> ascending unsigned)
__device__ __forceinline__ unsigned f2key(float f) {
    unsigned u = __float_as_uint(f);
    return (u & 0x80000000u) ? ~u : (u | 0x80000000u);
}
// relu(value) recovered from key
__device__ __forceinline__ float key2relu(unsigned k) {
    return (k & 0x80000000u) ? __uint_as_float(k ^ 0x80000000u) : 0.0f;
}

// Warp-parallel selection of the radix bin: finds unique b with
// F(b) >= k > F(b+1), where F(b) = sum_{j>=b} hist[j]. Warp 0 only.
__device__ __forceinline__ void select_bin(const unsigned* hist,
                                           volatile unsigned* s_prefix,
                                           volatile int* s_k,
                                           unsigned pfx, int shift, int tid)
{
    if (tid < 32) {
        const int lane = tid;
        unsigned hh[8];
        int lsum = 0;
        #pragma unroll
        for (int c = 0; c < 8; ++c) { hh[c] = hist[lane * 8 + c]; lsum += (int)hh[c]; }
        // inclusive suffix-sum across lanes (lane gets sum over lanes >= lane)
        int suf = lsum;
        #pragma unroll
        for (int off = 1; off < 32; off <<= 1) {
            int v = __shfl_down_sync(0xFFFFFFFFu, suf, off);
            if (lane + off < 32) suf += v;
        }
        const int above = suf - lsum;      // sum over lanes > lane
        const int k = *s_k;                // read before any lane writes
        int F = above;
        int foundb = -1, Fnext_at_found = 0;
        #pragma unroll
        for (int c = 7; c >= 0; --c) {
            int Fnext = F;
            F += (int)hh[c];
            if (F >= k && Fnext < k) { foundb = lane * 8 + c; Fnext_at_found = Fnext; }
        }
        if (foundb >= 0) {                 // exactly one lane matches
            *s_prefix = pfx | ((unsigned)foundb << shift);
            *s_k = k - Fnext_at_found;
        }
    }
}

__global__ __launch_bounds__(THREADS, 4)
void splittopk_kernel(const float* __restrict__ x, float* __restrict__ out)
{
    __shared__ unsigned       ckeys[CAP];   //  8 KB
    __shared__ unsigned short cidx[CAP];    //  4 KB
    __shared__ unsigned hist[256];
    __shared__ int s_cnt;
    __shared__ unsigned s_prefix;
    __shared__ int s_k;
    __shared__ int s_eqcnt;
    __shared__ int eq_idx[64];

    const int tid = threadIdx.x;
    const long long base = (long long)blockIdx.x * ELEMS;
    const float4* __restrict__ x4 = (const float4*)(x + base);
    float4* __restrict__ o4 = (float4*)(out + base);

    if (tid == 0) { s_cnt = 0; s_prefix = 0u; s_k = KSEL; s_eqcnt = 0; }
    __syncthreads();

    // ---- Phase 1: chunked stream: 4 batched loads -> 4 zero stores -> compact ----
    #pragma unroll
    for (int ch = 0; ch < NCHUNK; ++ch) {
        float4 r[CHUNK];
        #pragma unroll
        for (int j = 0; j < CHUNK; ++j)
            r[j] = __ldcs(&x4[(ch * CHUNK + j) * THREADS + tid]);
        #pragma unroll
        for (int j = 0; j < CHUNK; ++j)
            o4[(ch * CHUNK + j) * THREADS + tid] = make_float4(0.f, 0.f, 0.f, 0.f);
        #pragma unroll
        for (int j = 0; j < CHUNK; ++j) {
            const int p = (ch * CHUNK + j) * THREADS + tid;
            float vv[4] = {r[j].x, r[j].y, r[j].z, r[j].w};
            int nc = (vv[0] > THRESH) + (vv[1] > THRESH) +
                     (vv[2] > THRESH) + (vv[3] > THRESH);
            if (nc) {
                int pos = atomicAdd(&s_cnt, nc);
                #pragma unroll
                for (int c = 0; c < 4; ++c) {
                    if (vv[c] > THRESH) {
                        if (pos < CAP) {
                            ckeys[pos] = f2key(vv[c]);
                            cidx[pos]  = (unsigned short)(p * 4 + c);
                        }
                        ++pos;
                    }
                }
            }
        }
    }
    __syncthreads();

    const int cnt = s_cnt;

    if (cnt >= KSEL && cnt <= CAP) {
        // ======== FAST PATH: radix-select over ~hundreds of candidates ========
        #pragma unroll
        for (int pass = 0; pass < 4; ++pass) {
            const int shift = 24 - pass * 8;
            if (tid < 256) hist[tid] = 0u;
            __syncthreads();
            const unsigned pmask = (pass == 0) ? 0u : (0xFFFFFFFFu << (shift + 8));
            const unsigned pfx = s_prefix;
            for (int i = tid; i < cnt; i += THREADS) {
                unsigned k = ckeys[i];
                if ((k & pmask) == pfx)
                    atomicAdd(&hist[(k >> shift) & 255u], 1u);
            }
            __syncthreads();
            select_bin(hist, &s_prefix, &s_k, pfx, shift, tid);
            __syncthreads();
        }
        const unsigned T = s_prefix;
        const int kneed  = s_k;
        const float vT   = key2relu(T);

        for (int i = tid; i < cnt; i += THREADS) {
            unsigned k = ckeys[i];
            if (k > T) {
                out[base + cidx[i]] = key2relu(k);
            } else if (k == T) {
                int pq = atomicAdd(&s_eqcnt, 1);
                if (pq < 64) eq_idx[pq] = cidx[i];
            }
        }
        __syncthreads();

        const int eqc = s_eqcnt;
        if (eqc == kneed) {
            if (tid < eqc) out[base + eq_idx[tid]] = vT;
        } else {
            // fp32 tie at threshold: keep kneed smallest original indices
            for (int i = tid; i < cnt; i += THREADS) {
                if (ckeys[i] == T) {
                    int my = cidx[i];
                    int rank = 0;
                    for (int j = 0; j < cnt; ++j)
                        rank += (ckeys[j] == T && cidx[j] < my);
                    if (rank < kneed) out[base + my] = vT;
                }
            }
        }
    } else {
        // ======== COLD PATH: exact full radix-select reading from global ========
        #pragma unroll
        for (int pass = 0; pass < 4; ++pass) {
            const int shift = 24 - pass * 8;
            if (tid < 256) hist[tid] = 0u;
            __syncthreads();
            const unsigned pmask = (pass == 0) ? 0u : (0xFFFFFFFFu << (shift + 8));
            const unsigned pfx = s_prefix;
            for (int i = tid; i < ELEMS; i += THREADS) {
                unsigned k = f2key(x[base + i]);
                if ((k & pmask) == pfx)
                    atomicAdd(&hist[(k >> shift) & 255u], 1u);
            }
            __syncthreads();
            select_bin(hist, &s_prefix, &s_k, pfx, shift, tid);
            __syncthreads();
        }
        const unsigned T = s_prefix;
        const int kneed  = s_k;
        const float vT   = key2relu(T);

        for (int i = tid; i < ELEMS; i += THREADS) {
            unsigned k = f2key(x[base + i]);
            if (k > T) {
                out[base + i] = key2relu(k);
            } else if (k == T) {
                int pq = atomicAdd(&s_eqcnt, 1);
                if (pq < 64) eq_idx[pq] = i;
            }
        }
        __syncthreads();

        const int eqc = s_eqcnt;
        if (eqc == kneed) {
            if (tid < eqc) out[base + eq_idx[tid]] = vT;
        } else {
            for (int i = tid; i < ELEMS; i += THREADS) {
                if (f2key(x[base + i]) == T) {
                    int rank = 0;
                    for (int j = 0; j < i; ++j) rank += (f2key(x[base + j]) == T);
                    if (rank < kneed) out[base + i] = vT;
                }
            }
        }
    }
}

extern "C" void kernel_launch(void* const* d_in, const int* in_sizes, int n_in,
                              void* d_out, int out_size) {
    const float* x = (const float*)d_in[0];
    float* out = (float*)d_out;
    int nblocks = out_size / ELEMS;   // 4096 rows * 2 partitions = 8192
    splittopk_kernel<<<nblocks, THREADS>>>(x, out);
}